// round 1
// baseline (speedup 1.0000x reference)
#include <cuda_runtime.h>
#include <math_constants.h>

// Problem constants
#define N_ROWS 4096
#define V_SIZE 50000
#define D_DIM  300

// Flash tiling
#define BM 32          // query rows per CTA
#define BT 64          // vocab rows per K-tile
#define DPAD 309       // odd smem row stride: 309 mod 32 = 21 (coprime) -> conflict-free K reads
#define PSTRIDE 65     // P tile row stride (odd)
#define NTHREADS 256

// scratch for Y = words @ W
__device__ float g_Y[N_ROWS * D_DIM];

// ---------------------------------------------------------------------------
// Kernel 1: Y = words @ W   (4096x300 @ 300x300) — classic 16x16 tiled SGEMM
// ---------------------------------------------------------------------------
__global__ void y_gemm_kernel(const float* __restrict__ A,   // words [4096,300]
                              const float* __restrict__ B) { // W     [300,300]
    __shared__ float As[16][16];
    __shared__ float Bs[16][17];
    const int tx = threadIdx.x, ty = threadIdx.y;
    const int row = blockIdx.y * 16 + ty;     // always < 4096 (grid exact)
    const int col = blockIdx.x * 16 + tx;     // may exceed 300
    float acc = 0.f;
    for (int k0 = 0; k0 < D_DIM; k0 += 16) {
        As[ty][tx] = (k0 + tx < D_DIM) ? A[row * D_DIM + k0 + tx] : 0.f;
        Bs[ty][tx] = (k0 + ty < D_DIM && col < D_DIM) ? B[(k0 + ty) * D_DIM + col] : 0.f;
        __syncthreads();
#pragma unroll
        for (int kk = 0; kk < 16; ++kk) acc += As[ty][kk] * Bs[kk][tx];
        __syncthreads();
    }
    if (col < D_DIM) g_Y[row * D_DIM + col] = acc;
}

// ---------------------------------------------------------------------------
// Kernel 2: fused flash-softmax over the vocabulary (+ default key epilogue)
//   per CTA: 32 query rows, stream vocab in 64-row tiles, online softmax,
//   O accumulators live in registers (2 rows x 19 d-slots per thread).
// ---------------------------------------------------------------------------
__global__ void __launch_bounds__(NTHREADS, 1)
flash_kernel(const float* __restrict__ words,
             const float* __restrict__ vocab,
             const float* __restrict__ de,      // default_embed [300]
             float* __restrict__ out) {
    extern __shared__ float sm[];
    float* Qs       = sm;                        // BM * DPAD
    float* Ks       = Qs + BM * DPAD;            // BT * DPAD
    float* Ps       = Ks + BT * DPAD;            // BM * PSTRIDE
    float* sm_m     = Ps + BM * PSTRIDE;         // BM
    float* sm_l     = sm_m + BM;                 // BM
    float* sm_alpha = sm_l + BM;                 // BM
    float* sm_sdef  = sm_alpha + BM;             // BM

    const int tid = threadIdx.x;
    const int r0  = blockIdx.x * BM;

    // ---- load Q tile from g_Y, zero the d-padding ----
    for (int idx = tid; idx < BM * D_DIM; idx += NTHREADS) {
        int r = idx / D_DIM;
        int d = idx - r * D_DIM;
        Qs[r * DPAD + d] = g_Y[(r0 + r) * D_DIM + d];
    }
    for (int idx = tid; idx < BM * (DPAD - D_DIM); idx += NTHREADS) {
        int r = idx / (DPAD - D_DIM);
        int d = D_DIM + (idx - r * (DPAD - D_DIM));
        Qs[r * DPAD + d] = 0.f;
    }
    for (int idx = tid; idx < BT * (DPAD - D_DIM); idx += NTHREADS) {
        int r = idx / (DPAD - D_DIM);
        int d = D_DIM + (idx - r * (DPAD - D_DIM));
        Ks[r * DPAD + d] = 0.f;   // written once; data loads only touch d<300
    }
    if (tid < BM) { sm_m[tid] = -CUDART_INF_F; sm_l[tid] = 0.f; }
    __syncthreads();

    // ---- default-key score per row (1 warp, once per CTA) ----
    if (tid < BM) {
        float s = 0.f;
        for (int d = 0; d < D_DIM; ++d) s += Qs[tid * DPAD + d] * __ldg(&de[d]);
        sm_sdef[tid] = s;
    }

    // thread tiling: tr = row-pair group (rows 2tr,2tr+1), tc = col/d group
    const int tr = tid >> 4;   // 0..15
    const int tc = tid & 15;   // 0..15

    // O accumulators: rows {2tr, 2tr+1}, d = tc + 16*j, j=0..18 (covers 0..303)
    float acc[2][19];
#pragma unroll
    for (int i = 0; i < 2; ++i)
#pragma unroll
        for (int j = 0; j < 19; ++j) acc[i][j] = 0.f;

    const int ntiles = (V_SIZE + BT - 1) / BT;   // 782

    for (int kt = 0; kt < ntiles; ++kt) {
        const int base  = kt * BT;
        const int valid = min(BT, V_SIZE - base);

        // ---- load K tile: 64x300 floats, incremental (c,d) bookkeeping ----
        {
            int c = 0, d = tid;                       // tid < 256 < 300
            long gidx = (long)base * D_DIM + tid;
            int saddr = d;                            // c*DPAD + d
#pragma unroll 1
            for (int it = 0; it < (BT * D_DIM) / NTHREADS; ++it) {  // 75 iters
                float v = 0.f;
                if (base + c < V_SIZE) v = vocab[gidx];
                Ks[saddr] = v;
                gidx += NTHREADS;
                d += NTHREADS;
                saddr += NTHREADS;
                if (d >= D_DIM) { d -= D_DIM; ++c; saddr += (DPAD - D_DIM); }
            }
        }
        __syncthreads();

        // ---- S = Q @ K^T : each thread 2 rows x 4 cols (cols tc+16j) ----
        float s[2][4];
#pragma unroll
        for (int i = 0; i < 2; ++i)
#pragma unroll
            for (int j = 0; j < 4; ++j) s[i][j] = 0.f;

        {
            const float* qp0 = &Qs[(2 * tr) * DPAD];
            const float* qp1 = qp0 + DPAD;
            const float* kr0 = &Ks[(tc     ) * DPAD];
            const float* kr1 = &Ks[(tc + 16) * DPAD];
            const float* kr2 = &Ks[(tc + 32) * DPAD];
            const float* kr3 = &Ks[(tc + 48) * DPAD];
#pragma unroll 4
            for (int d = 0; d < D_DIM; ++d) {
                float q0 = qp0[d], q1 = qp1[d];
                float k0 = kr0[d], k1 = kr1[d], k2 = kr2[d], k3 = kr3[d];
                s[0][0] += q0 * k0; s[0][1] += q0 * k1;
                s[0][2] += q0 * k2; s[0][3] += q0 * k3;
                s[1][0] += q1 * k0; s[1][1] += q1 * k1;
                s[1][2] += q1 * k2; s[1][3] += q1 * k3;
            }
        }
#pragma unroll
        for (int i = 0; i < 2; ++i)
#pragma unroll
            for (int j = 0; j < 4; ++j)
                Ps[(2 * tr + i) * PSTRIDE + tc + 16 * j] = s[i][j];
        __syncthreads();

        // ---- online softmax update: 8 threads per row ----
        {
            const int r = tid >> 3, g = tid & 7;
            float* prow = &Ps[r * PSTRIDE];
            float mloc = -CUDART_INF_F;
            for (int c = g; c < valid; c += 8) mloc = fmaxf(mloc, prow[c]);
            mloc = fmaxf(mloc, __shfl_xor_sync(0xffffffffu, mloc, 1));
            mloc = fmaxf(mloc, __shfl_xor_sync(0xffffffffu, mloc, 2));
            mloc = fmaxf(mloc, __shfl_xor_sync(0xffffffffu, mloc, 4));
            const float m_old = sm_m[r];
            const float m_new = fmaxf(m_old, mloc);
            float sum = 0.f;
            for (int c = g; c < BT; c += 8) {
                float p = (c < valid) ? __expf(prow[c] - m_new) : 0.f;
                prow[c] = p;
                sum += p;
            }
            sum += __shfl_xor_sync(0xffffffffu, sum, 1);
            sum += __shfl_xor_sync(0xffffffffu, sum, 2);
            sum += __shfl_xor_sync(0xffffffffu, sum, 4);
            if (g == 0) {
                float a = __expf(m_old - m_new);   // 0 on first tile (m_old=-inf)
                sm_alpha[r] = a;
                sm_l[r] = sm_l[r] * a + sum;
                sm_m[r] = m_new;
            }
        }
        __syncthreads();

        // ---- O = O*alpha + P @ K : thread owns rows {2tr,2tr+1}, d=tc+16j ----
        {
            const float a0 = sm_alpha[2 * tr];
            const float a1 = sm_alpha[2 * tr + 1];
#pragma unroll
            for (int j = 0; j < 19; ++j) { acc[0][j] *= a0; acc[1][j] *= a1; }

            const float* p0 = &Ps[(2 * tr) * PSTRIDE];
            const float* p1 = p0 + PSTRIDE;
            const float* krow = &Ks[tc];
#pragma unroll 2
            for (int c = 0; c < BT; ++c) {
                float pa = p0[c], pb = p1[c];
#pragma unroll
                for (int j = 0; j < 19; ++j) {
                    float kv = krow[16 * j];
                    acc[0][j] += pa * kv;
                    acc[1][j] += pb * kv;
                }
                krow += DPAD;
            }
        }
        __syncthreads();   // protect Ks/Ps before next tile
    }

    // ---- epilogue: add default key (value = words row), normalize, store ----
#pragma unroll
    for (int i = 0; i < 2; ++i) {
        const int r = 2 * tr + i;
        const float pdef = __expf(sm_sdef[r] - sm_m[r]);
        const float inv  = 1.f / (sm_l[r] + pdef);
        const int grow = r0 + r;
        const float* wrow = &words[(long)grow * D_DIM];
        float* orow = &out[(long)grow * D_DIM];
#pragma unroll
        for (int j = 0; j < 19; ++j) {
            int d = tc + 16 * j;
            if (d < D_DIM)
                orow[d] = (acc[i][j] + pdef * wrow[d]) * inv;
        }
    }
}

// ---------------------------------------------------------------------------
// kernel_launch
// ---------------------------------------------------------------------------
extern "C" void kernel_launch(void* const* d_in, const int* in_sizes, int n_in,
                              void* d_out, int out_size) {
    const float* words = nullptr;
    const float* vocab = nullptr;
    const float* de    = nullptr;
    const float* W     = nullptr;
    for (int i = 0; i < n_in; ++i) {
        switch (in_sizes[i]) {
            case N_ROWS * D_DIM: words = (const float*)d_in[i]; break;   // 1,228,800
            case V_SIZE * D_DIM: vocab = (const float*)d_in[i]; break;   // 15,000,000
            case D_DIM:          de    = (const float*)d_in[i]; break;   // 300
            case D_DIM * D_DIM:  W     = (const float*)d_in[i]; break;   // 90,000
            default: break;
        }
    }
    float* out = (float*)d_out;

    // Y = words @ W
    dim3 yb(16, 16);
    dim3 yg((D_DIM + 15) / 16, N_ROWS / 16);
    y_gemm_kernel<<<yg, yb>>>(words, W);

    // fused flash pass
    const int smem_bytes = (BM * DPAD + BT * DPAD + BM * PSTRIDE + 4 * BM) * (int)sizeof(float);
    cudaFuncSetAttribute(flash_kernel, cudaFuncAttributeMaxDynamicSharedMemorySize, smem_bytes);
    flash_kernel<<<N_ROWS / BM, NTHREADS, smem_bytes>>>(words, vocab, de, out);
}

// round 5
// speedup vs baseline: 8.0204x; 8.0204x over previous
#include <cuda_runtime.h>
#include <cuda_bf16.h>
#include <math_constants.h>
#include <cstdint>

// ---------------------------------------------------------------------------
// Problem constants
// ---------------------------------------------------------------------------
#define N_ROWS 4096
#define V_SIZE 50000
#define D_DIM  300
#define KP     320      // padded depth (multiple of 64)
#define VP     50048    // padded vocab count = 391*128
#define DOUT   384      // padded output width = 3*128
#define NSPLIT 5        // gemm2 K-splits

// ---------------------------------------------------------------------------
// Scratch (__device__ globals; no dynamic allocation allowed)
// ---------------------------------------------------------------------------
__device__ float         g_Y   [N_ROWS * KP];
__device__ __nv_bfloat16 g_Yhi [N_ROWS * KP];
__device__ __nv_bfloat16 g_Ylo [N_ROWS * KP];
__device__ __nv_bfloat16 g_Vhi [(size_t)VP * KP];
__device__ __nv_bfloat16 g_Vlo [(size_t)VP * KP];
__device__ __nv_bfloat16 g_VThi[(size_t)DOUT * VP];
__device__ __nv_bfloat16 g_VTlo[(size_t)DOUT * VP];
__device__ float         g_S   [(size_t)N_ROWS * VP];
__device__ __nv_bfloat16 g_Phi [(size_t)N_ROWS * VP];
__device__ __nv_bfloat16 g_Plo [(size_t)N_ROWS * VP];
__device__ float         g_m   [N_ROWS];
__device__ float         g_l   [N_ROWS];
__device__ float         g_sdef[N_ROWS];
__device__ float         g_U   [NSPLIT][N_ROWS * DOUT];

// ---------------------------------------------------------------------------
// HMMA wrapper: D += A(16x16 bf16, row) * B(16x8 bf16, col), fp32 accum
// ---------------------------------------------------------------------------
__device__ __forceinline__ void mma16816(float* c, const uint32_t* a, const uint32_t* b) {
    asm volatile(
        "mma.sync.aligned.m16n8k16.row.col.f32.bf16.bf16.f32 "
        "{%0,%1,%2,%3}, {%4,%5,%6,%7}, {%8,%9}, {%0,%1,%2,%3};"
        : "+f"(c[0]), "+f"(c[1]), "+f"(c[2]), "+f"(c[3])
        : "r"(a[0]), "r"(a[1]), "r"(a[2]), "r"(a[3]), "r"(b[0]), "r"(b[1]));
}

// ---------------------------------------------------------------------------
// smem tile geometry: [128 rows][64 bf16] with stride 72 bf16 (=36 words)
// ---------------------------------------------------------------------------
#define TSTRIDE_W 36                       // words per row
#define TILE_W    (128 * TSTRIDE_W)        // 4608 words = 18432 bytes per tile
#define GEMM_SMEM (4 * TILE_W * 4)         // 4 tiles (Ahi,Alo,Bhi,Blo) = 73728 B

// copy one [128 x 64 bf16] tile from gmem (row stride = srcStride elems)
__device__ __forceinline__ void copy_tile(uint32_t* dst, const __nv_bfloat16* __restrict__ src,
                                          size_t srcStride, int tid) {
#pragma unroll
    for (int it = 0; it < 4; ++it) {
        const int i = tid + it * 256;
        const int row = i >> 3, q = i & 7;       // q: which 8-elem (16B) piece
        uint4 v = *(const uint4*)(src + (size_t)row * srcStride + q * 8);
        *(uint4*)(dst + row * TSTRIDE_W + q * 4) = v;
    }
}

// ---------------------------------------------------------------------------
// Core CTA-tile GEMM body (shared by both GEMMs).
// Computes acc[4][4][4] for this thread over nchunk K-chunks of 64.
// A: [m0..m0+127][K] row-major (hi/lo), B: [n0..n0+127][K] row-major (hi/lo).
// ---------------------------------------------------------------------------
struct Frag { float acc[4][4][4]; };

__device__ __forceinline__ void gemm_body(
        float acc[4][4][4],
        const __nv_bfloat16* Ahi, const __nv_bfloat16* Alo, size_t strideA,
        const __nv_bfloat16* Bhi, const __nv_bfloat16* Blo, size_t strideB,
        int nchunk, uint32_t* sA_hi, uint32_t* sA_lo, uint32_t* sB_hi, uint32_t* sB_lo) {
    const int tid = threadIdx.x;
    const int wid = tid >> 5, lane = tid & 31;
    const int g = lane >> 2, t = lane & 3;
    const int wm0 = (wid >> 2) * 64;         // warp m-origin within CTA tile
    const int wn0 = (wid & 3) * 32;          // warp n-origin

#pragma unroll
    for (int i = 0; i < 4; ++i)
#pragma unroll
        for (int j = 0; j < 4; ++j)
#pragma unroll
            for (int f = 0; f < 4; ++f) acc[i][j][f] = 0.f;

    for (int ch = 0; ch < nchunk; ++ch) {
        __syncthreads();
        const size_t k0 = (size_t)ch * 64;
        copy_tile(sA_hi, Ahi + k0, strideA, tid);
        copy_tile(sA_lo, Alo + k0, strideA, tid);
        copy_tile(sB_hi, Bhi + k0, strideB, tid);
        copy_tile(sB_lo, Blo + k0, strideB, tid);
        __syncthreads();

#pragma unroll
        for (int ks = 0; ks < 4; ++ks) {     // four k16 steps per 64-chunk
            const int kw = ks * 8 + t;       // word offset within row
            uint32_t ah[4][4], al[4][4];
#pragma unroll
            for (int i = 0; i < 4; ++i) {
                const int r0 = (wm0 + 16 * i + g) * TSTRIDE_W;
                const int r1 = r0 + 8 * TSTRIDE_W;
                ah[i][0] = sA_hi[r0 + kw];     ah[i][1] = sA_hi[r1 + kw];
                ah[i][2] = sA_hi[r0 + kw + 4]; ah[i][3] = sA_hi[r1 + kw + 4];
                al[i][0] = sA_lo[r0 + kw];     al[i][1] = sA_lo[r1 + kw];
                al[i][2] = sA_lo[r0 + kw + 4]; al[i][3] = sA_lo[r1 + kw + 4];
            }
            uint32_t bh[4][2], bl[4][2];
#pragma unroll
            for (int j = 0; j < 4; ++j) {
                const int rn = (wn0 + 8 * j + g) * TSTRIDE_W;
                bh[j][0] = sB_hi[rn + kw]; bh[j][1] = sB_hi[rn + kw + 4];
                bl[j][0] = sB_lo[rn + kw]; bl[j][1] = sB_lo[rn + kw + 4];
            }
#pragma unroll
            for (int i = 0; i < 4; ++i)
#pragma unroll
                for (int j = 0; j < 4; ++j) {
                    mma16816(acc[i][j], ah[i], bh[j]);   // hi*hi
                    mma16816(acc[i][j], ah[i], bl[j]);   // hi*lo
                    mma16816(acc[i][j], al[i], bh[j]);   // lo*hi
                }
        }
    }
}

// ---------------------------------------------------------------------------
// Kernel 1: Y = words @ W, zero-padded to [4096 x 320], with bf16 hi/lo split
// ---------------------------------------------------------------------------
__global__ void y_prep_kernel(const float* __restrict__ A,   // words [4096,300]
                              const float* __restrict__ B) { // W     [300,300]
    __shared__ float As[16][16];
    __shared__ float Bs[16][17];
    const int tx = threadIdx.x, ty = threadIdx.y;
    const int row = blockIdx.y * 16 + ty;     // < 4096
    const int col = blockIdx.x * 16 + tx;     // < 320
    float acc = 0.f;
    for (int k0 = 0; k0 < D_DIM; k0 += 16) {
        As[ty][tx] = (k0 + tx < D_DIM) ? A[row * D_DIM + k0 + tx] : 0.f;
        Bs[ty][tx] = (k0 + ty < D_DIM && col < D_DIM) ? B[(k0 + ty) * D_DIM + col] : 0.f;
        __syncthreads();
#pragma unroll
        for (int kk = 0; kk < 16; ++kk) acc += As[ty][kk] * Bs[kk][tx];
        __syncthreads();
    }
    const int idx = row * KP + col;
    g_Y[idx] = acc;
    __nv_bfloat16 h = __float2bfloat16(acc);
    g_Yhi[idx] = h;
    g_Ylo[idx] = __float2bfloat16(acc - __bfloat162float(h));
}

// ---------------------------------------------------------------------------
// Kernel 2a/2b: vocab splits (K-major [VP x KP] and transposed [DOUT x VP])
// ---------------------------------------------------------------------------
__global__ void v_prep_kernel(const float* __restrict__ vocab) {
    const int idx = blockIdx.x * 256 + threadIdx.x;
    const int v = idx / KP, d = idx - v * KP;
    float val = (v < V_SIZE && d < D_DIM) ? vocab[(size_t)v * D_DIM + d] : 0.f;
    __nv_bfloat16 h = __float2bfloat16(val);
    g_Vhi[idx] = h;
    g_Vlo[idx] = __float2bfloat16(val - __bfloat162float(h));
}

__global__ void vt_prep_kernel(const float* __restrict__ vocab) {
    const int idx = blockIdx.x * 256 + threadIdx.x;
    const int d = idx / VP, v = idx - d * VP;
    float val = (v < V_SIZE && d < D_DIM) ? vocab[(size_t)v * D_DIM + d] : 0.f;
    __nv_bfloat16 h = __float2bfloat16(val);
    g_VThi[idx] = h;
    g_VTlo[idx] = __float2bfloat16(val - __bfloat162float(h));
}

// ---------------------------------------------------------------------------
// Kernel 3: sdef[r] = Y[r] . default_embed  (one warp per row)
// ---------------------------------------------------------------------------
__global__ void sdef_kernel(const float* __restrict__ de) {
    const int w = (blockIdx.x * blockDim.x + threadIdx.x) >> 5;
    const int lane = threadIdx.x & 31;
    if (w >= N_ROWS) return;
    float s = 0.f;
    for (int d = lane; d < D_DIM; d += 32) s += g_Y[w * KP + d] * de[d];
#pragma unroll
    for (int o = 16; o; o >>= 1) s += __shfl_xor_sync(0xffffffffu, s, o);
    if (lane == 0) g_sdef[w] = s;
}

// ---------------------------------------------------------------------------
// Kernel 4: GEMM-1  S[4096 x 50048] = Y(hi/lo) @ Vocab(hi/lo)^T
// ---------------------------------------------------------------------------
__global__ void __launch_bounds__(256, 1) gemm1_kernel() {
    extern __shared__ uint32_t smw[];
    uint32_t* sA_hi = smw;
    uint32_t* sA_lo = smw + TILE_W;
    uint32_t* sB_hi = smw + 2 * TILE_W;
    uint32_t* sB_lo = smw + 3 * TILE_W;
    const int v0 = blockIdx.x * 128, m0 = blockIdx.y * 128;

    float acc[4][4][4];
    gemm_body(acc,
              g_Yhi + (size_t)m0 * KP, g_Ylo + (size_t)m0 * KP, KP,
              g_Vhi + (size_t)v0 * KP, g_Vlo + (size_t)v0 * KP, KP,
              KP / 64, sA_hi, sA_lo, sB_hi, sB_lo);

    const int tid = threadIdx.x, wid = tid >> 5, lane = tid & 31;
    const int g = lane >> 2, t = lane & 3;
    const int wm0 = (wid >> 2) * 64, wn0 = (wid & 3) * 32;
#pragma unroll
    for (int i = 0; i < 4; ++i) {
        const size_t r0 = (size_t)(m0 + wm0 + 16 * i + g);
#pragma unroll
        for (int j = 0; j < 4; ++j) {
            const size_t cc = (size_t)(v0 + wn0 + 8 * j + 2 * t);
            *(float2*)(g_S + r0 * VP + cc)       = make_float2(acc[i][j][0], acc[i][j][1]);
            *(float2*)(g_S + (r0 + 8) * VP + cc) = make_float2(acc[i][j][2], acc[i][j][3]);
        }
    }
}

// ---------------------------------------------------------------------------
// Kernel 5: per-row online max + sum-exp over the 50000 valid scores
// ---------------------------------------------------------------------------
__global__ void reduce_kernel() {
    const int r = blockIdx.x;
    const int tid = threadIdx.x;
    const float* row = g_S + (size_t)r * VP;
    float m = -CUDART_INF_F, l = 0.f;
    for (int c = tid; c < V_SIZE; c += 256) {
        const float s = row[c];
        if (s > m) { l = l * __expf(m - s) + 1.f; m = s; }
        else       { l += __expf(s - m); }
    }
#pragma unroll
    for (int o = 16; o; o >>= 1) {
        const float m2 = __shfl_xor_sync(0xffffffffu, m, o);
        const float l2 = __shfl_xor_sync(0xffffffffu, l, o);
        const float mn = fmaxf(m, m2);
        l = l * __expf(m - mn) + l2 * __expf(m2 - mn);
        m = mn;
    }
    __shared__ float sm8[8], sl8[8];
    if ((tid & 31) == 0) { sm8[tid >> 5] = m; sl8[tid >> 5] = l; }
    __syncthreads();
    if (tid == 0) {
        float M = sm8[0], L = sl8[0];
#pragma unroll
        for (int w = 1; w < 8; ++w) {
            const float mn = fmaxf(M, sm8[w]);
            L = L * __expf(M - mn) + sl8[w] * __expf(sm8[w] - mn);
            M = mn;
        }
        g_m[r] = M; g_l[r] = L;
    }
}

// ---------------------------------------------------------------------------
// Kernel 6: P~ = exp(S - m), split into bf16 hi/lo
// ---------------------------------------------------------------------------
__global__ void expsplit_kernel() {
    const int idx = blockIdx.x * 256 + threadIdx.x;
    const int r = idx / (VP / 4);
    const int c4 = idx - r * (VP / 4);
    const int c = c4 * 4;
    const float mrow = g_m[r];
    const float4 s = *(const float4*)(g_S + (size_t)r * VP + c);
    float p[4];
    p[0] = (c + 0 < V_SIZE) ? __expf(s.x - mrow) : 0.f;
    p[1] = (c + 1 < V_SIZE) ? __expf(s.y - mrow) : 0.f;
    p[2] = (c + 2 < V_SIZE) ? __expf(s.z - mrow) : 0.f;
    p[3] = (c + 3 < V_SIZE) ? __expf(s.w - mrow) : 0.f;
    unsigned hi[4], lo[4];
#pragma unroll
    for (int j = 0; j < 4; ++j) {
        const __nv_bfloat16 h = __float2bfloat16(p[j]);
        hi[j] = (unsigned)__bfloat16_as_ushort(h);
        lo[j] = (unsigned)__bfloat16_as_ushort(__float2bfloat16(p[j] - __bfloat162float(h)));
    }
    uint2 hv, lv;
    hv.x = hi[0] | (hi[1] << 16); hv.y = hi[2] | (hi[3] << 16);
    lv.x = lo[0] | (lo[1] << 16); lv.y = lo[2] | (lo[3] << 16);
    *(uint2*)(g_Phi + (size_t)r * VP + c) = hv;
    *(uint2*)(g_Plo + (size_t)r * VP + c) = lv;
}

// ---------------------------------------------------------------------------
// Kernel 7: GEMM-2  U[split] = P~(hi/lo) @ Vocab(hi/lo); K split over vocab.
// grid: (DOUT/128, N_ROWS/128, NSPLIT); separate buffers -> deterministic.
// ---------------------------------------------------------------------------
__global__ void __launch_bounds__(256, 1) gemm2_kernel() {
    extern __shared__ uint32_t smw[];
    uint32_t* sA_hi = smw;
    uint32_t* sA_lo = smw + TILE_W;
    uint32_t* sB_hi = smw + 2 * TILE_W;
    uint32_t* sB_lo = smw + 3 * TILE_W;
    const int n0 = blockIdx.x * 128, m0 = blockIdx.y * 128, sp = blockIdx.z;

    // 782 chunks of 64 split across NSPLIT: base 156, first 2 splits get +1
    const int base = 782 / NSPLIT;            // 156
    const int rem  = 782 % NSPLIT;            // 2
    const int cbeg = sp * base + min(sp, rem);
    const int nch  = base + (sp < rem ? 1 : 0);
    const size_t k0 = (size_t)cbeg * 64;

    float acc[4][4][4];
    gemm_body(acc,
              g_Phi  + (size_t)m0 * VP + k0, g_Plo  + (size_t)m0 * VP + k0, VP,
              g_VThi + (size_t)n0 * VP + k0, g_VTlo + (size_t)n0 * VP + k0, VP,
              nch, sA_hi, sA_lo, sB_hi, sB_lo);

    const int tid = threadIdx.x, wid = tid >> 5, lane = tid & 31;
    const int g = lane >> 2, t = lane & 3;
    const int wm0 = (wid >> 2) * 64, wn0 = (wid & 3) * 32;
    float* U = g_U[sp];
#pragma unroll
    for (int i = 0; i < 4; ++i) {
        const int r0 = m0 + wm0 + 16 * i + g;
#pragma unroll
        for (int j = 0; j < 4; ++j) {
            const int cc = n0 + wn0 + 8 * j + 2 * t;
            *(float2*)(U + (size_t)r0 * DOUT + cc)       = make_float2(acc[i][j][0], acc[i][j][1]);
            *(float2*)(U + (size_t)(r0 + 8) * DOUT + cc) = make_float2(acc[i][j][2], acc[i][j][3]);
        }
    }
}

// ---------------------------------------------------------------------------
// Kernel 8: final blend + normalize
// out[r][d] = (sum_s U[s][r][d] + pdef * words[r][d]) / (l + pdef)
// ---------------------------------------------------------------------------
__global__ void final_kernel(const float* __restrict__ words, float* __restrict__ out) {
    const int r = blockIdx.x;
    const int d = threadIdx.x;
    if (d >= D_DIM) return;
    const float m = g_m[r];
    const float l = g_l[r];
    const float pdef = __expf(g_sdef[r] - m);
    const float inv = 1.f / (l + pdef);
    const int ui = r * DOUT + d;
    float u = 0.f;
#pragma unroll
    for (int s = 0; s < NSPLIT; ++s) u += g_U[s][ui];
    out[(size_t)r * D_DIM + d] = (u + pdef * words[(size_t)r * D_DIM + d]) * inv;
}

// ---------------------------------------------------------------------------
// kernel_launch
// ---------------------------------------------------------------------------
extern "C" void kernel_launch(void* const* d_in, const int* in_sizes, int n_in,
                              void* d_out, int out_size) {
    const float* words = nullptr;
    const float* vocab = nullptr;
    const float* de    = nullptr;
    const float* W     = nullptr;
    for (int i = 0; i < n_in; ++i) {
        switch (in_sizes[i]) {
            case N_ROWS * D_DIM: words = (const float*)d_in[i]; break;
            case V_SIZE * D_DIM: vocab = (const float*)d_in[i]; break;
            case D_DIM:          de    = (const float*)d_in[i]; break;
            case D_DIM * D_DIM:  W     = (const float*)d_in[i]; break;
            default: break;
        }
    }
    float* out = (float*)d_out;

    // 1. Y = words @ W (+ hi/lo split, zero-padded to KP)
    y_prep_kernel<<<dim3(KP / 16, N_ROWS / 16), dim3(16, 16)>>>(words, W);

    // 2. vocab splits
    v_prep_kernel<<<(VP * KP) / 256, 256>>>(vocab);
    vt_prep_kernel<<<(DOUT * VP) / 256, 256>>>(vocab);

    // 3. default-key scores
    sdef_kernel<<<(N_ROWS * 32) / 256, 256>>>(de);

    // 4. GEMM-1: scores
    cudaFuncSetAttribute(gemm1_kernel, cudaFuncAttributeMaxDynamicSharedMemorySize, GEMM_SMEM);
    gemm1_kernel<<<dim3(VP / 128, N_ROWS / 128), 256, GEMM_SMEM>>>();

    // 5. softmax stats
    reduce_kernel<<<N_ROWS, 256>>>();

    // 6. exp + split
    expsplit_kernel<<<(N_ROWS * (VP / 4)) / 256, 256>>>();

    // 7. GEMM-2: unnormalized output (K-split)
    cudaFuncSetAttribute(gemm2_kernel, cudaFuncAttributeMaxDynamicSharedMemorySize, GEMM_SMEM);
    gemm2_kernel<<<dim3(DOUT / 128, N_ROWS / 128, NSPLIT), 256, GEMM_SMEM>>>();

    // 8. blend + normalize
    final_kernel<<<N_ROWS, 320>>>(words, out);
}

// round 10
// speedup vs baseline: 9.0020x; 1.1224x over previous
#include <cuda_runtime.h>
#include <cuda_bf16.h>
#include <math_constants.h>
#include <cstdint>

// ---------------------------------------------------------------------------
// Problem constants
// ---------------------------------------------------------------------------
#define N_ROWS 4096
#define V_SIZE 50000
#define D_DIM  300
#define KP     320      // padded depth (multiple of 64)
#define VP     50048    // padded vocab count = 391*128
#define DOUT   384      // padded output width = 3*128
#define NSPLIT 5        // gemm2 K-splits

// ---------------------------------------------------------------------------
// Scratch (__device__ globals; no dynamic allocation allowed)
// ---------------------------------------------------------------------------
__device__ float         g_Y   [N_ROWS * KP];
__device__ __nv_bfloat16 g_Yhi [N_ROWS * KP];
__device__ __nv_bfloat16 g_Ylo [N_ROWS * KP];
__device__ __nv_bfloat16 g_Vhi [(size_t)VP * KP];
__device__ __nv_bfloat16 g_Vlo [(size_t)VP * KP];
__device__ __nv_bfloat16 g_VThi[(size_t)DOUT * VP];
__device__ __nv_bfloat16 g_VTlo[(size_t)DOUT * VP];
__device__ float         g_S   [(size_t)N_ROWS * VP];
__device__ __nv_bfloat16 g_Phi [(size_t)N_ROWS * VP];
__device__ __nv_bfloat16 g_Plo [(size_t)N_ROWS * VP];
__device__ float         g_m   [N_ROWS];
__device__ float         g_l   [N_ROWS];
__device__ float         g_sdef[N_ROWS];
__device__ float         g_U   [NSPLIT][N_ROWS * DOUT];

// ---------------------------------------------------------------------------
// HMMA wrapper: D += A(16x16 bf16, row) * B(16x8 bf16, col), fp32 accum
// ---------------------------------------------------------------------------
__device__ __forceinline__ void mma16816(float* c, const uint32_t* a, const uint32_t* b) {
    asm volatile(
        "mma.sync.aligned.m16n8k16.row.col.f32.bf16.bf16.f32 "
        "{%0,%1,%2,%3}, {%4,%5,%6,%7}, {%8,%9}, {%0,%1,%2,%3};"
        : "+f"(c[0]), "+f"(c[1]), "+f"(c[2]), "+f"(c[3])
        : "r"(a[0]), "r"(a[1]), "r"(a[2]), "r"(a[3]), "r"(b[0]), "r"(b[1]));
}

// ---------------------------------------------------------------------------
// smem tile geometry: [128 rows][64 bf16] with stride 72 bf16 (=36 words)
// 2-stage double buffer, 4 tiles/stage (Ahi,Alo,Bhi,Blo)
// ---------------------------------------------------------------------------
#define TSTRIDE_W 36                        // words per row
#define TILE_W    (128 * TSTRIDE_W)         // 4608 words = 18432 bytes per tile
#define STAGE_W   (4 * TILE_W)              // words per stage
#define GEMM_SMEM (2 * STAGE_W * 4)         // 147456 bytes

__device__ __forceinline__ uint32_t smem_u32(const void* p) {
    return (uint32_t)__cvta_generic_to_shared(p);
}

// async copy one [128 x 64 bf16] tile (16B per thread-op, 4 ops/thread)
__device__ __forceinline__ void copy_tile_async(uint32_t* dst,
                                                const __nv_bfloat16* __restrict__ src,
                                                size_t srcStride, int tid) {
#pragma unroll
    for (int it = 0; it < 4; ++it) {
        const int i = tid + it * 256;
        const int row = i >> 3, q = i & 7;        // q: which 16B piece of the row
        const uint32_t saddr = smem_u32(dst + row * TSTRIDE_W + q * 4);
        const void* gaddr = (const void*)(src + (size_t)row * srcStride + q * 8);
        asm volatile("cp.async.cg.shared.global [%0], [%1], 16;"
                     :: "r"(saddr), "l"(gaddr) : "memory");
    }
}

__device__ __forceinline__ void load_stage(uint32_t* st,
        const __nv_bfloat16* Ahi, const __nv_bfloat16* Alo, size_t sA,
        const __nv_bfloat16* Bhi, const __nv_bfloat16* Blo, size_t sB,
        size_t k0, int tid) {
    copy_tile_async(st,              Ahi + k0, sA, tid);
    copy_tile_async(st +     TILE_W, Alo + k0, sA, tid);
    copy_tile_async(st + 2 * TILE_W, Bhi + k0, sB, tid);
    copy_tile_async(st + 3 * TILE_W, Blo + k0, sB, tid);
    asm volatile("cp.async.commit_group;" ::: "memory");
}

// ---------------------------------------------------------------------------
// Core CTA-tile GEMM body (shared by both GEMMs), cp.async double-buffered.
// Computes acc[4][4][4] over nchunk K-chunks of 64.
// ---------------------------------------------------------------------------
__device__ __forceinline__ void gemm_body(
        float acc[4][4][4],
        const __nv_bfloat16* Ahi, const __nv_bfloat16* Alo, size_t strideA,
        const __nv_bfloat16* Bhi, const __nv_bfloat16* Blo, size_t strideB,
        int nchunk, uint32_t* smw) {
    const int tid = threadIdx.x;
    const int wid = tid >> 5, lane = tid & 31;
    const int g = lane >> 2, t = lane & 3;
    const int wm0 = (wid >> 2) * 64;         // warp m-origin within CTA tile
    const int wn0 = (wid & 3) * 32;          // warp n-origin

#pragma unroll
    for (int i = 0; i < 4; ++i)
#pragma unroll
        for (int j = 0; j < 4; ++j)
#pragma unroll
            for (int f = 0; f < 4; ++f) acc[i][j][f] = 0.f;

    // prefetch chunk 0 into stage 0
    load_stage(smw, Ahi, Alo, strideA, Bhi, Blo, strideB, 0, tid);

    for (int ch = 0; ch < nchunk; ++ch) {
        // prefetch next chunk into the other stage
        if (ch + 1 < nchunk) {
            load_stage(smw + ((ch + 1) & 1) * STAGE_W,
                       Ahi, Alo, strideA, Bhi, Blo, strideB,
                       (size_t)(ch + 1) * 64, tid);
            asm volatile("cp.async.wait_group 1;" ::: "memory");
        } else {
            asm volatile("cp.async.wait_group 0;" ::: "memory");
        }
        __syncthreads();

        uint32_t* st    = smw + (ch & 1) * STAGE_W;
        uint32_t* sA_hi = st;
        uint32_t* sA_lo = st + TILE_W;
        uint32_t* sB_hi = st + 2 * TILE_W;
        uint32_t* sB_lo = st + 3 * TILE_W;

#pragma unroll
        for (int ks = 0; ks < 4; ++ks) {     // four k16 steps per 64-chunk
            const int kw = ks * 8 + t;       // word offset within row
            uint32_t ah[4][4], al[4][4];
#pragma unroll
            for (int i = 0; i < 4; ++i) {
                const int r0 = (wm0 + 16 * i + g) * TSTRIDE_W;
                const int r1 = r0 + 8 * TSTRIDE_W;
                ah[i][0] = sA_hi[r0 + kw];     ah[i][1] = sA_hi[r1 + kw];
                ah[i][2] = sA_hi[r0 + kw + 4]; ah[i][3] = sA_hi[r1 + kw + 4];
                al[i][0] = sA_lo[r0 + kw];     al[i][1] = sA_lo[r1 + kw];
                al[i][2] = sA_lo[r0 + kw + 4]; al[i][3] = sA_lo[r1 + kw + 4];
            }
            uint32_t bh[4][2], bl[4][2];
#pragma unroll
            for (int j = 0; j < 4; ++j) {
                const int rn = (wn0 + 8 * j + g) * TSTRIDE_W;
                bh[j][0] = sB_hi[rn + kw]; bh[j][1] = sB_hi[rn + kw + 4];
                bl[j][0] = sB_lo[rn + kw]; bl[j][1] = sB_lo[rn + kw + 4];
            }
#pragma unroll
            for (int i = 0; i < 4; ++i)
#pragma unroll
                for (int j = 0; j < 4; ++j) {
                    mma16816(acc[i][j], ah[i], bh[j]);   // hi*hi
                    mma16816(acc[i][j], ah[i], bl[j]);   // hi*lo
                    mma16816(acc[i][j], al[i], bh[j]);   // lo*hi
                }
        }
        __syncthreads();   // stage (ch&1) free for reuse at ch+2 prefetch
    }
}

// ---------------------------------------------------------------------------
// Kernel 1: Y = words @ W, zero-padded to [4096 x 320], with bf16 hi/lo split
// ---------------------------------------------------------------------------
__global__ void y_prep_kernel(const float* __restrict__ A,   // words [4096,300]
                              const float* __restrict__ B) { // W     [300,300]
    __shared__ float As[16][16];
    __shared__ float Bs[16][17];
    const int tx = threadIdx.x, ty = threadIdx.y;
    const int row = blockIdx.y * 16 + ty;     // < 4096
    const int col = blockIdx.x * 16 + tx;     // < 320
    float acc = 0.f;
    for (int k0 = 0; k0 < D_DIM; k0 += 16) {
        As[ty][tx] = (k0 + tx < D_DIM) ? A[row * D_DIM + k0 + tx] : 0.f;
        Bs[ty][tx] = (k0 + ty < D_DIM && col < D_DIM) ? B[(k0 + ty) * D_DIM + col] : 0.f;
        __syncthreads();
#pragma unroll
        for (int kk = 0; kk < 16; ++kk) acc += As[ty][kk] * Bs[kk][tx];
        __syncthreads();
    }
    const int idx = row * KP + col;
    g_Y[idx] = acc;
    __nv_bfloat16 h = __float2bfloat16(acc);
    g_Yhi[idx] = h;
    g_Ylo[idx] = __float2bfloat16(acc - __bfloat162float(h));
}

// ---------------------------------------------------------------------------
// Kernel 2a/2b: vocab splits (K-major [VP x KP] and transposed [DOUT x VP])
// ---------------------------------------------------------------------------
__global__ void v_prep_kernel(const float* __restrict__ vocab) {
    const int idx = blockIdx.x * 256 + threadIdx.x;
    const int v = idx / KP, d = idx - v * KP;
    float val = (v < V_SIZE && d < D_DIM) ? vocab[(size_t)v * D_DIM + d] : 0.f;
    __nv_bfloat16 h = __float2bfloat16(val);
    g_Vhi[idx] = h;
    g_Vlo[idx] = __float2bfloat16(val - __bfloat162float(h));
}

__global__ void vt_prep_kernel(const float* __restrict__ vocab) {
    const int idx = blockIdx.x * 256 + threadIdx.x;
    const int d = idx / VP, v = idx - d * VP;
    float val = (v < V_SIZE && d < D_DIM) ? vocab[(size_t)v * D_DIM + d] : 0.f;
    __nv_bfloat16 h = __float2bfloat16(val);
    g_VThi[idx] = h;
    g_VTlo[idx] = __float2bfloat16(val - __bfloat162float(h));
}

// ---------------------------------------------------------------------------
// Kernel 3: sdef[r] = Y[r] . default_embed  (one warp per row)
// ---------------------------------------------------------------------------
__global__ void sdef_kernel(const float* __restrict__ de) {
    const int w = (blockIdx.x * blockDim.x + threadIdx.x) >> 5;
    const int lane = threadIdx.x & 31;
    if (w >= N_ROWS) return;
    float s = 0.f;
    for (int d = lane; d < D_DIM; d += 32) s += g_Y[w * KP + d] * de[d];
#pragma unroll
    for (int o = 16; o; o >>= 1) s += __shfl_xor_sync(0xffffffffu, s, o);
    if (lane == 0) g_sdef[w] = s;
}

// ---------------------------------------------------------------------------
// Kernel 4: GEMM-1  S[4096 x 50048] = Y(hi/lo) @ Vocab(hi/lo)^T
// ---------------------------------------------------------------------------
__global__ void __launch_bounds__(256, 1) gemm1_kernel() {
    extern __shared__ uint32_t smw[];
    const int v0 = blockIdx.x * 128, m0 = blockIdx.y * 128;

    float acc[4][4][4];
    gemm_body(acc,
              g_Yhi + (size_t)m0 * KP, g_Ylo + (size_t)m0 * KP, KP,
              g_Vhi + (size_t)v0 * KP, g_Vlo + (size_t)v0 * KP, KP,
              KP / 64, smw);

    const int tid = threadIdx.x, wid = tid >> 5, lane = tid & 31;
    const int g = lane >> 2, t = lane & 3;
    const int wm0 = (wid >> 2) * 64, wn0 = (wid & 3) * 32;
#pragma unroll
    for (int i = 0; i < 4; ++i) {
        const size_t r0 = (size_t)(m0 + wm0 + 16 * i + g);
#pragma unroll
        for (int j = 0; j < 4; ++j) {
            const size_t cc = (size_t)(v0 + wn0 + 8 * j + 2 * t);
            *(float2*)(g_S + r0 * VP + cc)       = make_float2(acc[i][j][0], acc[i][j][1]);
            *(float2*)(g_S + (r0 + 8) * VP + cc) = make_float2(acc[i][j][2], acc[i][j][3]);
        }
    }
}

// ---------------------------------------------------------------------------
// Kernel 5: per-row online max + sum-exp over the 50000 valid scores
// ---------------------------------------------------------------------------
__global__ void reduce_kernel() {
    const int r = blockIdx.x;
    const int tid = threadIdx.x;
    const float* row = g_S + (size_t)r * VP;
    float m = -CUDART_INF_F, l = 0.f;
    for (int c = tid; c < V_SIZE; c += 256) {
        const float s = row[c];
        if (s > m) { l = l * __expf(m - s) + 1.f; m = s; }
        else       { l += __expf(s - m); }
    }
#pragma unroll
    for (int o = 16; o; o >>= 1) {
        const float m2 = __shfl_xor_sync(0xffffffffu, m, o);
        const float l2 = __shfl_xor_sync(0xffffffffu, l, o);
        const float mn = fmaxf(m, m2);
        l = l * __expf(m - mn) + l2 * __expf(m2 - mn);
        m = mn;
    }
    __shared__ float sm8[8], sl8[8];
    if ((tid & 31) == 0) { sm8[tid >> 5] = m; sl8[tid >> 5] = l; }
    __syncthreads();
    if (tid == 0) {
        float M = sm8[0], L = sl8[0];
#pragma unroll
        for (int w = 1; w < 8; ++w) {
            const float mn = fmaxf(M, sm8[w]);
            L = L * __expf(M - mn) + sl8[w] * __expf(sm8[w] - mn);
            M = mn;
        }
        g_m[r] = M; g_l[r] = L;
    }
}

// ---------------------------------------------------------------------------
// Kernel 6: P~ = exp(S - m), split into bf16 hi/lo
// ---------------------------------------------------------------------------
__global__ void expsplit_kernel() {
    const int idx = blockIdx.x * 256 + threadIdx.x;
    const int r = idx / (VP / 4);
    const int c4 = idx - r * (VP / 4);
    const int c = c4 * 4;
    const float mrow = g_m[r];
    const float4 s = *(const float4*)(g_S + (size_t)r * VP + c);
    float p[4];
    p[0] = (c + 0 < V_SIZE) ? __expf(s.x - mrow) : 0.f;
    p[1] = (c + 1 < V_SIZE) ? __expf(s.y - mrow) : 0.f;
    p[2] = (c + 2 < V_SIZE) ? __expf(s.z - mrow) : 0.f;
    p[3] = (c + 3 < V_SIZE) ? __expf(s.w - mrow) : 0.f;
    unsigned hi[4], lo[4];
#pragma unroll
    for (int j = 0; j < 4; ++j) {
        const __nv_bfloat16 h = __float2bfloat16(p[j]);
        hi[j] = (unsigned)__bfloat16_as_ushort(h);
        lo[j] = (unsigned)__bfloat16_as_ushort(__float2bfloat16(p[j] - __bfloat162float(h)));
    }
    uint2 hv, lv;
    hv.x = hi[0] | (hi[1] << 16); hv.y = hi[2] | (hi[3] << 16);
    lv.x = lo[0] | (lo[1] << 16); lv.y = lo[2] | (lo[3] << 16);
    *(uint2*)(g_Phi + (size_t)r * VP + c) = hv;
    *(uint2*)(g_Plo + (size_t)r * VP + c) = lv;
}

// ---------------------------------------------------------------------------
// Kernel 7: GEMM-2  U[split] = P~(hi/lo) @ Vocab(hi/lo); K split over vocab.
// grid: (DOUT/128, N_ROWS/128, NSPLIT); separate buffers -> deterministic.
// ---------------------------------------------------------------------------
__global__ void __launch_bounds__(256, 1) gemm2_kernel() {
    extern __shared__ uint32_t smw[];
    const int n0 = blockIdx.x * 128, m0 = blockIdx.y * 128, sp = blockIdx.z;

    // 782 chunks of 64 split across NSPLIT
    const int base = 782 / NSPLIT;
    const int rem  = 782 % NSPLIT;
    const int cbeg = sp * base + min(sp, rem);
    const int nch  = base + (sp < rem ? 1 : 0);
    const size_t k0 = (size_t)cbeg * 64;

    float acc[4][4][4];
    gemm_body(acc,
              g_Phi  + (size_t)m0 * VP + k0, g_Plo  + (size_t)m0 * VP + k0, VP,
              g_VThi + (size_t)n0 * VP + k0, g_VTlo + (size_t)n0 * VP + k0, VP,
              nch, smw);

    const int tid = threadIdx.x, wid = tid >> 5, lane = tid & 31;
    const int g = lane >> 2, t = lane & 3;
    const int wm0 = (wid >> 2) * 64, wn0 = (wid & 3) * 32;
    float* U = g_U[sp];
#pragma unroll
    for (int i = 0; i < 4; ++i) {
        const int r0 = m0 + wm0 + 16 * i + g;
#pragma unroll
        for (int j = 0; j < 4; ++j) {
            const int cc = n0 + wn0 + 8 * j + 2 * t;
            *(float2*)(U + (size_t)r0 * DOUT + cc)       = make_float2(acc[i][j][0], acc[i][j][1]);
            *(float2*)(U + (size_t)(r0 + 8) * DOUT + cc) = make_float2(acc[i][j][2], acc[i][j][3]);
        }
    }
}

// ---------------------------------------------------------------------------
// Kernel 8: final blend + normalize
// ---------------------------------------------------------------------------
__global__ void final_kernel(const float* __restrict__ words, float* __restrict__ out) {
    const int r = blockIdx.x;
    const int d = threadIdx.x;
    if (d >= D_DIM) return;
    const float m = g_m[r];
    const float l = g_l[r];
    const float pdef = __expf(g_sdef[r] - m);
    const float inv = 1.f / (l + pdef);
    const int ui = r * DOUT + d;
    float u = 0.f;
#pragma unroll
    for (int s = 0; s < NSPLIT; ++s) u += g_U[s][ui];
    out[(size_t)r * D_DIM + d] = (u + pdef * words[(size_t)r * D_DIM + d]) * inv;
}

// ---------------------------------------------------------------------------
// kernel_launch
// ---------------------------------------------------------------------------
extern "C" void kernel_launch(void* const* d_in, const int* in_sizes, int n_in,
                              void* d_out, int out_size) {
    const float* words = nullptr;
    const float* vocab = nullptr;
    const float* de    = nullptr;
    const float* W     = nullptr;
    for (int i = 0; i < n_in; ++i) {
        switch (in_sizes[i]) {
            case N_ROWS * D_DIM: words = (const float*)d_in[i]; break;
            case V_SIZE * D_DIM: vocab = (const float*)d_in[i]; break;
            case D_DIM:          de    = (const float*)d_in[i]; break;
            case D_DIM * D_DIM:  W     = (const float*)d_in[i]; break;
            default: break;
        }
    }
    float* out = (float*)d_out;

    // 1. Y = words @ W (+ hi/lo split, zero-padded to KP)
    y_prep_kernel<<<dim3(KP / 16, N_ROWS / 16), dim3(16, 16)>>>(words, W);

    // 2. vocab splits
    v_prep_kernel<<<(VP * KP) / 256, 256>>>(vocab);
    vt_prep_kernel<<<(DOUT * VP) / 256, 256>>>(vocab);

    // 3. default-key scores
    sdef_kernel<<<(N_ROWS * 32) / 256, 256>>>(de);

    // 4. GEMM-1: scores
    cudaFuncSetAttribute(gemm1_kernel, cudaFuncAttributeMaxDynamicSharedMemorySize, GEMM_SMEM);
    gemm1_kernel<<<dim3(VP / 128, N_ROWS / 128), 256, GEMM_SMEM>>>();

    // 5. softmax stats
    reduce_kernel<<<N_ROWS, 256>>>();

    // 6. exp + split
    expsplit_kernel<<<(N_ROWS * (VP / 4)) / 256, 256>>>();

    // 7. GEMM-2: unnormalized output (K-split)
    cudaFuncSetAttribute(gemm2_kernel, cudaFuncAttributeMaxDynamicSharedMemorySize, GEMM_SMEM);
    gemm2_kernel<<<dim3(DOUT / 128, N_ROWS / 128, NSPLIT), 256, GEMM_SMEM>>>();

    // 8. blend + normalize
    final_kernel<<<N_ROWS, 320>>>(words, out);
}

// round 11
// speedup vs baseline: 9.5167x; 1.0572x over previous
#include <cuda_runtime.h>
#include <cuda_bf16.h>
#include <math_constants.h>
#include <cstdint>

// ---------------------------------------------------------------------------
// Problem constants
// ---------------------------------------------------------------------------
#define N_ROWS 4096
#define V_SIZE 50000
#define D_DIM  300
#define KP     320      // padded depth (multiple of 64)
#define VP     50048    // padded vocab count = 391*128
#define DOUT   384      // padded output width = 3*128
#define NSPLIT 5        // gemm2 K-splits
#define NVT    (VP / 128)   // 391 vocab tiles (gemm1 grid.x)
#define NLT    49           // expsplit col-blocks per row (49*1024 >= VP)

// ---------------------------------------------------------------------------
// Scratch (__device__ globals; no dynamic allocation allowed)
// ---------------------------------------------------------------------------
__device__ float         g_Y    [N_ROWS * KP];
__device__ __nv_bfloat16 g_Yhi  [N_ROWS * KP];
__device__ __nv_bfloat16 g_Ylo  [N_ROWS * KP];
__device__ __nv_bfloat16 g_Vhi  [(size_t)VP * KP];
__device__ __nv_bfloat16 g_Vlo  [(size_t)VP * KP];
__device__ __nv_bfloat16 g_VThi [(size_t)DOUT * VP];
__device__ __nv_bfloat16 g_VTlo [(size_t)DOUT * VP];
__device__ float         g_S    [(size_t)N_ROWS * VP];
__device__ __nv_bfloat16 g_Phi  [(size_t)N_ROWS * VP];
__device__ __nv_bfloat16 g_Plo  [(size_t)N_ROWS * VP];
__device__ float         g_mpart[(size_t)N_ROWS * NVT];
__device__ float         g_lpart[(size_t)N_ROWS * NLT];
__device__ float         g_m    [N_ROWS];
__device__ float         g_sdef [N_ROWS];
__device__ float         g_U    [NSPLIT][N_ROWS * DOUT];

// ---------------------------------------------------------------------------
// HMMA + ldmatrix wrappers
// ---------------------------------------------------------------------------
__device__ __forceinline__ void mma16816(float* c, const uint32_t* a, const uint32_t* b) {
    asm volatile(
        "mma.sync.aligned.m16n8k16.row.col.f32.bf16.bf16.f32 "
        "{%0,%1,%2,%3}, {%4,%5,%6,%7}, {%8,%9}, {%0,%1,%2,%3};"
        : "+f"(c[0]), "+f"(c[1]), "+f"(c[2]), "+f"(c[3])
        : "r"(a[0]), "r"(a[1]), "r"(a[2]), "r"(a[3]), "r"(b[0]), "r"(b[1]));
}

__device__ __forceinline__ void ldm_x4(uint32_t* r, uint32_t saddr) {
    asm volatile("ldmatrix.sync.aligned.m8n8.x4.shared.b16 {%0,%1,%2,%3}, [%4];"
                 : "=r"(r[0]), "=r"(r[1]), "=r"(r[2]), "=r"(r[3]) : "r"(saddr));
}

// ---------------------------------------------------------------------------
// smem tile geometry: [128 rows][64 bf16] stride 72 bf16 (=36 words = 144 B)
// 2-stage double buffer, 4 tiles/stage (Ahi,Alo,Bhi,Blo)
// ---------------------------------------------------------------------------
#define TSTRIDE_W 36
#define TSTRIDE_B 144
#define TILE_W    (128 * TSTRIDE_W)
#define TILE_B    (TILE_W * 4)
#define STAGE_W   (4 * TILE_W)
#define STAGE_B   (STAGE_W * 4)
#define GEMM_SMEM (2 * STAGE_B)             // 147456 bytes

__device__ __forceinline__ uint32_t smem_u32(const void* p) {
    return (uint32_t)__cvta_generic_to_shared(p);
}

__device__ __forceinline__ void copy_tile_async(uint32_t* dst,
                                                const __nv_bfloat16* __restrict__ src,
                                                size_t srcStride, int tid) {
#pragma unroll
    for (int it = 0; it < 4; ++it) {
        const int i = tid + it * 256;
        const int row = i >> 3, q = i & 7;
        const uint32_t saddr = smem_u32(dst + row * TSTRIDE_W + q * 4);
        const void* gaddr = (const void*)(src + (size_t)row * srcStride + q * 8);
        asm volatile("cp.async.cg.shared.global [%0], [%1], 16;"
                     :: "r"(saddr), "l"(gaddr) : "memory");
    }
}

__device__ __forceinline__ void load_stage(uint32_t* st,
        const __nv_bfloat16* Ahi, const __nv_bfloat16* Alo, size_t sA,
        const __nv_bfloat16* Bhi, const __nv_bfloat16* Blo, size_t sB,
        size_t k0, int tid) {
    copy_tile_async(st,              Ahi + k0, sA, tid);
    copy_tile_async(st +     TILE_W, Alo + k0, sA, tid);
    copy_tile_async(st + 2 * TILE_W, Bhi + k0, sB, tid);
    copy_tile_async(st + 3 * TILE_W, Blo + k0, sB, tid);
    asm volatile("cp.async.commit_group;" ::: "memory");
}

// ---------------------------------------------------------------------------
// Core CTA-tile GEMM body: cp.async double-buffered, ldmatrix fragments.
// ---------------------------------------------------------------------------
__device__ __forceinline__ void gemm_body(
        float acc[4][4][4],
        const __nv_bfloat16* Ahi, const __nv_bfloat16* Alo, size_t strideA,
        const __nv_bfloat16* Bhi, const __nv_bfloat16* Blo, size_t strideB,
        int nchunk, uint32_t* smw) {
    const int tid = threadIdx.x;
    const int wid = tid >> 5, lane = tid & 31;
    const int wm0 = (wid >> 2) * 64;         // warp m-origin within CTA tile
    const int wn0 = (wid & 3) * 32;          // warp n-origin

    // ldmatrix per-lane byte offsets (relative to tile base)
    // A x4: matrices (r0-7,k0),(r8-15,k0),(r0-7,k8),(r8-15,k8)
    const int aRow = (lane & 7) + ((lane >> 3) & 1) * 8;
    const int aKb  = (lane >> 4) * 16;
    // B x4: matrices (n0-7,k0),(n0-7,k8),(n8-15,k0),(n8-15,k8)
    const int bRow = (lane & 7) + (lane >> 4) * 8;
    const int bKb  = ((lane >> 3) & 1) * 16;

    uint32_t aoff[4], boff[2];
#pragma unroll
    for (int i = 0; i < 4; ++i)
        aoff[i] = (uint32_t)((wm0 + 16 * i + aRow) * TSTRIDE_B + aKb);
#pragma unroll
    for (int p = 0; p < 2; ++p)
        boff[p] = (uint32_t)((wn0 + 16 * p + bRow) * TSTRIDE_B + bKb);

    const uint32_t sbase = smem_u32(smw);

#pragma unroll
    for (int i = 0; i < 4; ++i)
#pragma unroll
        for (int j = 0; j < 4; ++j)
#pragma unroll
            for (int f = 0; f < 4; ++f) acc[i][j][f] = 0.f;

    load_stage(smw, Ahi, Alo, strideA, Bhi, Blo, strideB, 0, tid);

    for (int ch = 0; ch < nchunk; ++ch) {
        if (ch + 1 < nchunk) {
            load_stage(smw + ((ch + 1) & 1) * STAGE_W,
                       Ahi, Alo, strideA, Bhi, Blo, strideB,
                       (size_t)(ch + 1) * 64, tid);
            asm volatile("cp.async.wait_group 1;" ::: "memory");
        } else {
            asm volatile("cp.async.wait_group 0;" ::: "memory");
        }
        __syncthreads();

        const uint32_t st   = sbase + (ch & 1) * STAGE_B;
        const uint32_t stAh = st;
        const uint32_t stAl = st + TILE_B;
        const uint32_t stBh = st + 2 * TILE_B;
        const uint32_t stBl = st + 3 * TILE_B;

#pragma unroll
        for (int ks = 0; ks < 4; ++ks) {
            const uint32_t ko = (uint32_t)(ks * 32);
            uint32_t ah[4][4], al[4][4], bh[2][4], bl[2][4];
#pragma unroll
            for (int p = 0; p < 2; ++p) {
                ldm_x4(bh[p], stBh + boff[p] + ko);
                ldm_x4(bl[p], stBl + boff[p] + ko);
            }
#pragma unroll
            for (int i = 0; i < 4; ++i) {
                ldm_x4(ah[i], stAh + aoff[i] + ko);
                ldm_x4(al[i], stAl + aoff[i] + ko);
            }
#pragma unroll
            for (int i = 0; i < 4; ++i)
#pragma unroll
                for (int j = 0; j < 4; ++j) {
                    const uint32_t* pbh = &bh[j >> 1][(j & 1) * 2];
                    const uint32_t* pbl = &bl[j >> 1][(j & 1) * 2];
                    mma16816(acc[i][j], ah[i], pbh);   // hi*hi
                    mma16816(acc[i][j], ah[i], pbl);   // hi*lo
                    mma16816(acc[i][j], al[i], pbh);   // lo*hi
                }
        }
        __syncthreads();
    }
}

// ---------------------------------------------------------------------------
// Kernel 1: Y = words @ W, zero-padded to [4096 x 320], with bf16 hi/lo split
// ---------------------------------------------------------------------------
__global__ void y_prep_kernel(const float* __restrict__ A,
                              const float* __restrict__ B) {
    __shared__ float As[16][16];
    __shared__ float Bs[16][17];
    const int tx = threadIdx.x, ty = threadIdx.y;
    const int row = blockIdx.y * 16 + ty;
    const int col = blockIdx.x * 16 + tx;
    float acc = 0.f;
    for (int k0 = 0; k0 < D_DIM; k0 += 16) {
        As[ty][tx] = (k0 + tx < D_DIM) ? A[row * D_DIM + k0 + tx] : 0.f;
        Bs[ty][tx] = (k0 + ty < D_DIM && col < D_DIM) ? B[(k0 + ty) * D_DIM + col] : 0.f;
        __syncthreads();
#pragma unroll
        for (int kk = 0; kk < 16; ++kk) acc += As[ty][kk] * Bs[kk][tx];
        __syncthreads();
    }
    const int idx = row * KP + col;
    g_Y[idx] = acc;
    __nv_bfloat16 h = __float2bfloat16(acc);
    g_Yhi[idx] = h;
    g_Ylo[idx] = __float2bfloat16(acc - __bfloat162float(h));
}

// ---------------------------------------------------------------------------
// Kernel 2a/2b: vocab splits (K-major [VP x KP] and transposed [DOUT x VP])
// ---------------------------------------------------------------------------
__global__ void v_prep_kernel(const float* __restrict__ vocab) {
    const int idx = blockIdx.x * 256 + threadIdx.x;
    const int v = idx / KP, d = idx - v * KP;
    float val = (v < V_SIZE && d < D_DIM) ? vocab[(size_t)v * D_DIM + d] : 0.f;
    __nv_bfloat16 h = __float2bfloat16(val);
    g_Vhi[idx] = h;
    g_Vlo[idx] = __float2bfloat16(val - __bfloat162float(h));
}

__global__ void vt_prep_kernel(const float* __restrict__ vocab) {
    const int idx = blockIdx.x * 256 + threadIdx.x;
    const int d = idx / VP, v = idx - d * VP;
    float val = (v < V_SIZE && d < D_DIM) ? vocab[(size_t)v * D_DIM + d] : 0.f;
    __nv_bfloat16 h = __float2bfloat16(val);
    g_VThi[idx] = h;
    g_VTlo[idx] = __float2bfloat16(val - __bfloat162float(h));
}

// ---------------------------------------------------------------------------
// Kernel 3: sdef[r] = Y[r] . default_embed  (one warp per row)
// ---------------------------------------------------------------------------
__global__ void sdef_kernel(const float* __restrict__ de) {
    const int w = (blockIdx.x * blockDim.x + threadIdx.x) >> 5;
    const int lane = threadIdx.x & 31;
    if (w >= N_ROWS) return;
    float s = 0.f;
    for (int d = lane; d < D_DIM; d += 32) s += g_Y[w * KP + d] * de[d];
#pragma unroll
    for (int o = 16; o; o >>= 1) s += __shfl_xor_sync(0xffffffffu, s, o);
    if (lane == 0) g_sdef[w] = s;
}

// ---------------------------------------------------------------------------
// Kernel 4: GEMM-1  S = Y(hi/lo) @ Vocab(hi/lo)^T, fused per-tile row max
// ---------------------------------------------------------------------------
__global__ void __launch_bounds__(256, 1) gemm1_kernel() {
    extern __shared__ uint32_t smw[];
    const int v0 = blockIdx.x * 128, m0 = blockIdx.y * 128;

    float acc[4][4][4];
    gemm_body(acc,
              g_Yhi + (size_t)m0 * KP, g_Ylo + (size_t)m0 * KP, KP,
              g_Vhi + (size_t)v0 * KP, g_Vlo + (size_t)v0 * KP, KP,
              KP / 64, smw);

    const int tid = threadIdx.x, wid = tid >> 5, lane = tid & 31;
    const int g = lane >> 2, t = lane & 3;
    const int wm0 = (wid >> 2) * 64, wn0 = (wid & 3) * 32;

    // store S
#pragma unroll
    for (int i = 0; i < 4; ++i) {
        const size_t r0 = (size_t)(m0 + wm0 + 16 * i + g);
#pragma unroll
        for (int j = 0; j < 4; ++j) {
            const size_t cc = (size_t)(v0 + wn0 + 8 * j + 2 * t);
            *(float2*)(g_S + r0 * VP + cc)       = make_float2(acc[i][j][0], acc[i][j][1]);
            *(float2*)(g_S + (r0 + 8) * VP + cc) = make_float2(acc[i][j][2], acc[i][j][3]);
        }
    }

    // fused masked row-max over this 128-col tile
    float rm[4][2];
#pragma unroll
    for (int i = 0; i < 4; ++i) { rm[i][0] = -CUDART_INF_F; rm[i][1] = -CUDART_INF_F; }
#pragma unroll
    for (int i = 0; i < 4; ++i)
#pragma unroll
        for (int j = 0; j < 4; ++j) {
            const int c0 = v0 + wn0 + 8 * j + 2 * t;
            const float v00 = (c0     < V_SIZE) ? acc[i][j][0] : -CUDART_INF_F;
            const float v01 = (c0 + 1 < V_SIZE) ? acc[i][j][1] : -CUDART_INF_F;
            const float v10 = (c0     < V_SIZE) ? acc[i][j][2] : -CUDART_INF_F;
            const float v11 = (c0 + 1 < V_SIZE) ? acc[i][j][3] : -CUDART_INF_F;
            rm[i][0] = fmaxf(rm[i][0], fmaxf(v00, v01));
            rm[i][1] = fmaxf(rm[i][1], fmaxf(v10, v11));
        }
#pragma unroll
    for (int i = 0; i < 4; ++i)
#pragma unroll
        for (int h = 0; h < 2; ++h) {
            rm[i][h] = fmaxf(rm[i][h], __shfl_xor_sync(0xffffffffu, rm[i][h], 1));
            rm[i][h] = fmaxf(rm[i][h], __shfl_xor_sync(0xffffffffu, rm[i][h], 2));
        }
    float* red = (float*)smw;                 // [4 n-warp groups][128 rows]
    if (t == 0) {
#pragma unroll
        for (int i = 0; i < 4; ++i)
#pragma unroll
            for (int h = 0; h < 2; ++h)
                red[(wid & 3) * 128 + wm0 + 16 * i + g + 8 * h] = rm[i][h];
    }
    __syncthreads();
    if (tid < 128) {
        const float mx = fmaxf(fmaxf(red[tid], red[128 + tid]),
                               fmaxf(red[256 + tid], red[384 + tid]));
        g_mpart[(size_t)(m0 + tid) * NVT + blockIdx.x] = mx;
    }
}

// ---------------------------------------------------------------------------
// Kernel 5: g_m[r] = max over 391 tile maxima (one warp per row)
// ---------------------------------------------------------------------------
__global__ void reduce_m_kernel() {
    const int w = (blockIdx.x * blockDim.x + threadIdx.x) >> 5;
    const int lane = threadIdx.x & 31;
    if (w >= N_ROWS) return;
    float m = -CUDART_INF_F;
    for (int c = lane; c < NVT; c += 32) m = fmaxf(m, g_mpart[(size_t)w * NVT + c]);
#pragma unroll
    for (int o = 16; o; o >>= 1) m = fmaxf(m, __shfl_xor_sync(0xffffffffu, m, o));
    if (lane == 0) g_m[w] = m;
}

// ---------------------------------------------------------------------------
// Kernel 6: P~ = exp(S - m) -> bf16 hi/lo, with fused partial row sums
// grid (NLT, N_ROWS), 256 threads, 4 cols/thread
// ---------------------------------------------------------------------------
__global__ void expsplit_kernel() {
    const int r = blockIdx.y;
    const int tid = threadIdx.x;
    const int c = (blockIdx.x * 256 + tid) * 4;
    const float mrow = g_m[r];
    float lsum = 0.f;
    if (c < VP) {
        const float4 s = *(const float4*)(g_S + (size_t)r * VP + c);
        float p[4];
        p[0] = (c + 0 < V_SIZE) ? __expf(s.x - mrow) : 0.f;
        p[1] = (c + 1 < V_SIZE) ? __expf(s.y - mrow) : 0.f;
        p[2] = (c + 2 < V_SIZE) ? __expf(s.z - mrow) : 0.f;
        p[3] = (c + 3 < V_SIZE) ? __expf(s.w - mrow) : 0.f;
        lsum = (p[0] + p[1]) + (p[2] + p[3]);
        unsigned hi[4], lo[4];
#pragma unroll
        for (int j = 0; j < 4; ++j) {
            const __nv_bfloat16 h = __float2bfloat16(p[j]);
            hi[j] = (unsigned)__bfloat16_as_ushort(h);
            lo[j] = (unsigned)__bfloat16_as_ushort(__float2bfloat16(p[j] - __bfloat162float(h)));
        }
        uint2 hv, lv;
        hv.x = hi[0] | (hi[1] << 16); hv.y = hi[2] | (hi[3] << 16);
        lv.x = lo[0] | (lo[1] << 16); lv.y = lo[2] | (lo[3] << 16);
        *(uint2*)(g_Phi + (size_t)r * VP + c) = hv;
        *(uint2*)(g_Plo + (size_t)r * VP + c) = lv;
    }
    // block reduce lsum
#pragma unroll
    for (int o = 16; o; o >>= 1) lsum += __shfl_xor_sync(0xffffffffu, lsum, o);
    __shared__ float sl8[8];
    if ((tid & 31) == 0) sl8[tid >> 5] = lsum;
    __syncthreads();
    if (tid == 0) {
        float L = 0.f;
#pragma unroll
        for (int w = 0; w < 8; ++w) L += sl8[w];
        g_lpart[(size_t)r * NLT + blockIdx.x] = L;
    }
}

// ---------------------------------------------------------------------------
// Kernel 7: GEMM-2  U[split] = P~(hi/lo) @ Vocab(hi/lo); K split over vocab
// ---------------------------------------------------------------------------
__global__ void __launch_bounds__(256, 1) gemm2_kernel() {
    extern __shared__ uint32_t smw[];
    const int n0 = blockIdx.x * 128, m0 = blockIdx.y * 128, sp = blockIdx.z;

    const int base = 782 / NSPLIT;
    const int rem  = 782 % NSPLIT;
    const int cbeg = sp * base + min(sp, rem);
    const int nch  = base + (sp < rem ? 1 : 0);
    const size_t k0 = (size_t)cbeg * 64;

    float acc[4][4][4];
    gemm_body(acc,
              g_Phi  + (size_t)m0 * VP + k0, g_Plo  + (size_t)m0 * VP + k0, VP,
              g_VThi + (size_t)n0 * VP + k0, g_VTlo + (size_t)n0 * VP + k0, VP,
              nch, smw);

    const int tid = threadIdx.x, wid = tid >> 5, lane = tid & 31;
    const int g = lane >> 2, t = lane & 3;
    const int wm0 = (wid >> 2) * 64, wn0 = (wid & 3) * 32;
    float* U = g_U[sp];
#pragma unroll
    for (int i = 0; i < 4; ++i) {
        const int r0 = m0 + wm0 + 16 * i + g;
#pragma unroll
        for (int j = 0; j < 4; ++j) {
            const int cc = n0 + wn0 + 8 * j + 2 * t;
            *(float2*)(U + (size_t)r0 * DOUT + cc)       = make_float2(acc[i][j][0], acc[i][j][1]);
            *(float2*)(U + (size_t)(r0 + 8) * DOUT + cc) = make_float2(acc[i][j][2], acc[i][j][3]);
        }
    }
}

// ---------------------------------------------------------------------------
// Kernel 8: final blend + normalize (l reduced from partials in-block)
// ---------------------------------------------------------------------------
__global__ void final_kernel(const float* __restrict__ words, float* __restrict__ out) {
    const int r = blockIdx.x;
    const int tid = threadIdx.x;
    __shared__ float s_l;
    if (tid < 32) {
        float L = 0.f;
        for (int c = tid; c < NLT; c += 32) L += g_lpart[(size_t)r * NLT + c];
#pragma unroll
        for (int o = 16; o; o >>= 1) L += __shfl_xor_sync(0xffffffffu, L, o);
        if (tid == 0) s_l = L;
    }
    __syncthreads();
    if (tid >= D_DIM) return;
    const float m = g_m[r];
    const float pdef = __expf(g_sdef[r] - m);
    const float inv = 1.f / (s_l + pdef);
    const int ui = r * DOUT + tid;
    float u = 0.f;
#pragma unroll
    for (int s = 0; s < NSPLIT; ++s) u += g_U[s][ui];
    out[(size_t)r * D_DIM + tid] = (u + pdef * words[(size_t)r * D_DIM + tid]) * inv;
}

// ---------------------------------------------------------------------------
// kernel_launch
// ---------------------------------------------------------------------------
extern "C" void kernel_launch(void* const* d_in, const int* in_sizes, int n_in,
                              void* d_out, int out_size) {
    const float* words = nullptr;
    const float* vocab = nullptr;
    const float* de    = nullptr;
    const float* W     = nullptr;
    for (int i = 0; i < n_in; ++i) {
        switch (in_sizes[i]) {
            case N_ROWS * D_DIM: words = (const float*)d_in[i]; break;
            case V_SIZE * D_DIM: vocab = (const float*)d_in[i]; break;
            case D_DIM:          de    = (const float*)d_in[i]; break;
            case D_DIM * D_DIM:  W     = (const float*)d_in[i]; break;
            default: break;
        }
    }
    float* out = (float*)d_out;

    y_prep_kernel<<<dim3(KP / 16, N_ROWS / 16), dim3(16, 16)>>>(words, W);
    v_prep_kernel<<<(VP * KP) / 256, 256>>>(vocab);
    vt_prep_kernel<<<(DOUT * VP) / 256, 256>>>(vocab);
    sdef_kernel<<<(N_ROWS * 32) / 256, 256>>>(de);

    cudaFuncSetAttribute(gemm1_kernel, cudaFuncAttributeMaxDynamicSharedMemorySize, GEMM_SMEM);
    gemm1_kernel<<<dim3(NVT, N_ROWS / 128), 256, GEMM_SMEM>>>();

    reduce_m_kernel<<<(N_ROWS * 32) / 256, 256>>>();

    expsplit_kernel<<<dim3(NLT, N_ROWS), 256>>>();

    cudaFuncSetAttribute(gemm2_kernel, cudaFuncAttributeMaxDynamicSharedMemorySize, GEMM_SMEM);
    gemm2_kernel<<<dim3(DOUT / 128, N_ROWS / 128, NSPLIT), 256, GEMM_SMEM>>>();

    final_kernel<<<N_ROWS, 320>>>(words, out);
}

// round 13
// speedup vs baseline: 10.8215x; 1.1371x over previous
#include <cuda_runtime.h>
#include <cuda_bf16.h>
#include <math_constants.h>
#include <cstdint>

// ---------------------------------------------------------------------------
// Problem constants
// ---------------------------------------------------------------------------
#define N_ROWS 4096
#define V_SIZE 50000
#define D_DIM  300
#define KP     320      // padded depth (multiple of 64)
#define VP     50048    // padded vocab count = 391*128
#define DOUT   384      // padded output width = 3*128
#define NSPLIT 6        // gemm2 K-splits
#define NVT    (VP / 128)   // 391 vocab tiles (gemm1 grid.x)
#define NLT    49           // expsplit col-blocks per row (49*1024 >= VP)

#define BM_T   256      // CTA tile rows   (A)
#define BN_T   128      // CTA tile cols   (B)
#define NTH    512      // threads per CTA (16 warps)

// ---------------------------------------------------------------------------
// Scratch (__device__ globals; no dynamic allocation allowed)
// ---------------------------------------------------------------------------
__device__ float         g_Y    [N_ROWS * KP];
__device__ __nv_bfloat16 g_Yhi  [N_ROWS * KP];
__device__ __nv_bfloat16 g_Ylo  [N_ROWS * KP];
__device__ __nv_bfloat16 g_Vhi  [(size_t)VP * KP];
__device__ __nv_bfloat16 g_Vlo  [(size_t)VP * KP];
__device__ __nv_bfloat16 g_VThi [(size_t)DOUT * VP];
__device__ __nv_bfloat16 g_VTlo [(size_t)DOUT * VP];
__device__ float         g_S    [(size_t)N_ROWS * VP];
__device__ __nv_bfloat16 g_Phi  [(size_t)N_ROWS * VP];
__device__ __nv_bfloat16 g_Plo  [(size_t)N_ROWS * VP];
__device__ float         g_mpart[(size_t)N_ROWS * NVT];
__device__ float         g_lpart[(size_t)N_ROWS * NLT];
__device__ float         g_m    [N_ROWS];
__device__ float         g_sdef [N_ROWS];
__device__ float         g_U    [NSPLIT][N_ROWS * DOUT];

// ---------------------------------------------------------------------------
// HMMA + ldmatrix wrappers
// ---------------------------------------------------------------------------
__device__ __forceinline__ void mma16816(float* c, const uint32_t* a, const uint32_t* b) {
    asm volatile(
        "mma.sync.aligned.m16n8k16.row.col.f32.bf16.bf16.f32 "
        "{%0,%1,%2,%3}, {%4,%5,%6,%7}, {%8,%9}, {%0,%1,%2,%3};"
        : "+f"(c[0]), "+f"(c[1]), "+f"(c[2]), "+f"(c[3])
        : "r"(a[0]), "r"(a[1]), "r"(a[2]), "r"(a[3]), "r"(b[0]), "r"(b[1]));
}

__device__ __forceinline__ void ldm_x4(uint32_t* r, uint32_t saddr) {
    asm volatile("ldmatrix.sync.aligned.m8n8.x4.shared.b16 {%0,%1,%2,%3}, [%4];"
                 : "=r"(r[0]), "=r"(r[1]), "=r"(r[2]), "=r"(r[3]) : "r"(saddr));
}

// ---------------------------------------------------------------------------
// smem tile geometry: rows x [64 bf16] with stride 72 bf16 (=36 words = 144 B)
// stage = Ahi[256r] Alo[256r] Bhi[128r] Blo[128r]; 2-stage double buffer
// ---------------------------------------------------------------------------
#define TSTRIDE_W 36
#define TSTRIDE_B 144
#define ATILE_W   (BM_T * TSTRIDE_W)        // 9216 words  (36864 B)
#define BTILE_W   (BN_T * TSTRIDE_W)        // 4608 words  (18432 B)
#define STAGE_W   (2 * ATILE_W + 2 * BTILE_W)   // 27648 words (110592 B)
#define STAGE_B   (STAGE_W * 4)
#define GEMM_SMEM (2 * STAGE_B)             // 221184 bytes

__device__ __forceinline__ uint32_t smem_u32(const void* p) {
    return (uint32_t)__cvta_generic_to_shared(p);
}

template <int ROWS>
__device__ __forceinline__ void copy_tile_async(uint32_t* dst,
                                                const __nv_bfloat16* __restrict__ src,
                                                size_t srcStride, int tid) {
#pragma unroll
    for (int it = 0; it < (ROWS * 8) / NTH; ++it) {
        const int i = tid + it * NTH;
        const int row = i >> 3, q = i & 7;
        const uint32_t saddr = smem_u32(dst + row * TSTRIDE_W + q * 4);
        const void* gaddr = (const void*)(src + (size_t)row * srcStride + q * 8);
        asm volatile("cp.async.cg.shared.global [%0], [%1], 16;"
                     :: "r"(saddr), "l"(gaddr) : "memory");
    }
}

__device__ __forceinline__ void load_stage(uint32_t* st,
        const __nv_bfloat16* Ahi, const __nv_bfloat16* Alo, size_t sA,
        const __nv_bfloat16* Bhi, const __nv_bfloat16* Blo, size_t sB,
        size_t k0, int tid) {
    copy_tile_async<BM_T>(st,                           Ahi + k0, sA, tid);
    copy_tile_async<BM_T>(st + ATILE_W,                 Alo + k0, sA, tid);
    copy_tile_async<BN_T>(st + 2 * ATILE_W,             Bhi + k0, sB, tid);
    copy_tile_async<BN_T>(st + 2 * ATILE_W + BTILE_W,   Blo + k0, sB, tid);
    asm volatile("cp.async.commit_group;" ::: "memory");
}

// ---------------------------------------------------------------------------
// Core CTA-tile GEMM body: 256x128 tile, 16 warps (4m x 4n), warp tile 64x32.
// ---------------------------------------------------------------------------
__device__ __forceinline__ void gemm_body(
        float acc[4][4][4],
        const __nv_bfloat16* Ahi, const __nv_bfloat16* Alo, size_t strideA,
        const __nv_bfloat16* Bhi, const __nv_bfloat16* Blo, size_t strideB,
        int nchunk, uint32_t* smw) {
    const int tid = threadIdx.x;
    const int wid = tid >> 5, lane = tid & 31;
    const int wm0 = (wid >> 2) * 64;         // 4 m-groups: 0,64,128,192
    const int wn0 = (wid & 3) * 32;          // 4 n-groups: 0,32,64,96

    // ldmatrix per-lane byte offsets (relative to tile base)
    const int aRow = (lane & 7) + ((lane >> 3) & 1) * 8;
    const int aKb  = (lane >> 4) * 16;
    const int bRow = (lane & 7) + (lane >> 4) * 8;
    const int bKb  = ((lane >> 3) & 1) * 16;

    uint32_t aoff[4], boff[2];
#pragma unroll
    for (int i = 0; i < 4; ++i)
        aoff[i] = (uint32_t)((wm0 + 16 * i + aRow) * TSTRIDE_B + aKb);
#pragma unroll
    for (int p = 0; p < 2; ++p)
        boff[p] = (uint32_t)((wn0 + 16 * p + bRow) * TSTRIDE_B + bKb);

    const uint32_t sbase = smem_u32(smw);

#pragma unroll
    for (int i = 0; i < 4; ++i)
#pragma unroll
        for (int j = 0; j < 4; ++j)
#pragma unroll
            for (int f = 0; f < 4; ++f) acc[i][j][f] = 0.f;

    load_stage(smw, Ahi, Alo, strideA, Bhi, Blo, strideB, 0, tid);

    for (int ch = 0; ch < nchunk; ++ch) {
        if (ch + 1 < nchunk) {
            load_stage(smw + ((ch + 1) & 1) * STAGE_W,
                       Ahi, Alo, strideA, Bhi, Blo, strideB,
                       (size_t)(ch + 1) * 64, tid);
            asm volatile("cp.async.wait_group 1;" ::: "memory");
        } else {
            asm volatile("cp.async.wait_group 0;" ::: "memory");
        }
        __syncthreads();

        const uint32_t st   = sbase + (ch & 1) * STAGE_B;
        const uint32_t stAh = st;
        const uint32_t stAl = st + ATILE_W * 4;
        const uint32_t stBh = st + 2 * ATILE_W * 4;
        const uint32_t stBl = st + (2 * ATILE_W + BTILE_W) * 4;

#pragma unroll
        for (int ks = 0; ks < 4; ++ks) {
            const uint32_t ko = (uint32_t)(ks * 32);
            uint32_t ah[4][4], al[4][4], bh[2][4], bl[2][4];
#pragma unroll
            for (int p = 0; p < 2; ++p) {
                ldm_x4(bh[p], stBh + boff[p] + ko);
                ldm_x4(bl[p], stBl + boff[p] + ko);
            }
#pragma unroll
            for (int i = 0; i < 4; ++i) {
                ldm_x4(ah[i], stAh + aoff[i] + ko);
                ldm_x4(al[i], stAl + aoff[i] + ko);
            }
#pragma unroll
            for (int i = 0; i < 4; ++i)
#pragma unroll
                for (int j = 0; j < 4; ++j) {
                    const uint32_t* pbh = &bh[j >> 1][(j & 1) * 2];
                    const uint32_t* pbl = &bl[j >> 1][(j & 1) * 2];
                    mma16816(acc[i][j], ah[i], pbh);   // hi*hi
                    mma16816(acc[i][j], ah[i], pbl);   // hi*lo
                    mma16816(acc[i][j], al[i], pbh);   // lo*hi
                }
        }
        __syncthreads();
    }
}

// ---------------------------------------------------------------------------
// Kernel 1: Y = words @ W, zero-padded to [4096 x 320], with bf16 hi/lo split
// ---------------------------------------------------------------------------
__global__ void y_prep_kernel(const float* __restrict__ A,
                              const float* __restrict__ B) {
    __shared__ float As[16][16];
    __shared__ float Bs[16][17];
    const int tx = threadIdx.x, ty = threadIdx.y;
    const int row = blockIdx.y * 16 + ty;
    const int col = blockIdx.x * 16 + tx;
    float acc = 0.f;
    for (int k0 = 0; k0 < D_DIM; k0 += 16) {
        As[ty][tx] = (k0 + tx < D_DIM) ? A[row * D_DIM + k0 + tx] : 0.f;
        Bs[ty][tx] = (k0 + ty < D_DIM && col < D_DIM) ? B[(k0 + ty) * D_DIM + col] : 0.f;
        __syncthreads();
#pragma unroll
        for (int kk = 0; kk < 16; ++kk) acc += As[ty][kk] * Bs[kk][tx];
        __syncthreads();
    }
    const int idx = row * KP + col;
    g_Y[idx] = acc;
    __nv_bfloat16 h = __float2bfloat16(acc);
    g_Yhi[idx] = h;
    g_Ylo[idx] = __float2bfloat16(acc - __bfloat162float(h));
}

// ---------------------------------------------------------------------------
// Kernel 2a/2b: vocab splits (K-major [VP x KP] and transposed [DOUT x VP])
// ---------------------------------------------------------------------------
__global__ void v_prep_kernel(const float* __restrict__ vocab) {
    const int idx = blockIdx.x * 256 + threadIdx.x;
    const int v = idx / KP, d = idx - v * KP;
    float val = (v < V_SIZE && d < D_DIM) ? vocab[(size_t)v * D_DIM + d] : 0.f;
    __nv_bfloat16 h = __float2bfloat16(val);
    g_Vhi[idx] = h;
    g_Vlo[idx] = __float2bfloat16(val - __bfloat162float(h));
}

__global__ void vt_prep_kernel(const float* __restrict__ vocab) {
    const int idx = blockIdx.x * 256 + threadIdx.x;
    const int d = idx / VP, v = idx - d * VP;
    float val = (v < V_SIZE && d < D_DIM) ? vocab[(size_t)v * D_DIM + d] : 0.f;
    __nv_bfloat16 h = __float2bfloat16(val);
    g_VThi[idx] = h;
    g_VTlo[idx] = __float2bfloat16(val - __bfloat162float(h));
}

// ---------------------------------------------------------------------------
// Kernel 3: sdef[r] = Y[r] . default_embed  (one warp per row)
// ---------------------------------------------------------------------------
__global__ void sdef_kernel(const float* __restrict__ de) {
    const int w = (blockIdx.x * blockDim.x + threadIdx.x) >> 5;
    const int lane = threadIdx.x & 31;
    if (w >= N_ROWS) return;
    float s = 0.f;
    for (int d = lane; d < D_DIM; d += 32) s += g_Y[w * KP + d] * de[d];
#pragma unroll
    for (int o = 16; o; o >>= 1) s += __shfl_xor_sync(0xffffffffu, s, o);
    if (lane == 0) g_sdef[w] = s;
}

// ---------------------------------------------------------------------------
// Kernel 4: GEMM-1  S = Y(hi/lo) @ Vocab(hi/lo)^T, fused per-tile row max
// grid (NVT, N_ROWS/256), 512 threads
// ---------------------------------------------------------------------------
__global__ void __launch_bounds__(NTH, 1) gemm1_kernel() {
    extern __shared__ uint32_t smw[];
    const int v0 = blockIdx.x * BN_T, m0 = blockIdx.y * BM_T;

    float acc[4][4][4];
    gemm_body(acc,
              g_Yhi + (size_t)m0 * KP, g_Ylo + (size_t)m0 * KP, KP,
              g_Vhi + (size_t)v0 * KP, g_Vlo + (size_t)v0 * KP, KP,
              KP / 64, smw);

    const int tid = threadIdx.x, wid = tid >> 5, lane = tid & 31;
    const int g = lane >> 2, t = lane & 3;
    const int wm0 = (wid >> 2) * 64, wn0 = (wid & 3) * 32;

    // store S
#pragma unroll
    for (int i = 0; i < 4; ++i) {
        const size_t r0 = (size_t)(m0 + wm0 + 16 * i + g);
#pragma unroll
        for (int j = 0; j < 4; ++j) {
            const size_t cc = (size_t)(v0 + wn0 + 8 * j + 2 * t);
            *(float2*)(g_S + r0 * VP + cc)       = make_float2(acc[i][j][0], acc[i][j][1]);
            *(float2*)(g_S + (r0 + 8) * VP + cc) = make_float2(acc[i][j][2], acc[i][j][3]);
        }
    }

    // fused masked row-max over this 128-col tile
    float rm[4][2];
#pragma unroll
    for (int i = 0; i < 4; ++i) { rm[i][0] = -CUDART_INF_F; rm[i][1] = -CUDART_INF_F; }
#pragma unroll
    for (int i = 0; i < 4; ++i)
#pragma unroll
        for (int j = 0; j < 4; ++j) {
            const int c0 = v0 + wn0 + 8 * j + 2 * t;
            const float v00 = (c0     < V_SIZE) ? acc[i][j][0] : -CUDART_INF_F;
            const float v01 = (c0 + 1 < V_SIZE) ? acc[i][j][1] : -CUDART_INF_F;
            const float v10 = (c0     < V_SIZE) ? acc[i][j][2] : -CUDART_INF_F;
            const float v11 = (c0 + 1 < V_SIZE) ? acc[i][j][3] : -CUDART_INF_F;
            rm[i][0] = fmaxf(rm[i][0], fmaxf(v00, v01));
            rm[i][1] = fmaxf(rm[i][1], fmaxf(v10, v11));
        }
#pragma unroll
    for (int i = 0; i < 4; ++i)
#pragma unroll
        for (int h = 0; h < 2; ++h) {
            rm[i][h] = fmaxf(rm[i][h], __shfl_xor_sync(0xffffffffu, rm[i][h], 1));
            rm[i][h] = fmaxf(rm[i][h], __shfl_xor_sync(0xffffffffu, rm[i][h], 2));
        }
    float* red = (float*)smw;                 // [4 n-groups][256 rows]
    __syncthreads();
    if (t == 0) {
#pragma unroll
        for (int i = 0; i < 4; ++i)
#pragma unroll
            for (int h = 0; h < 2; ++h)
                red[(wid & 3) * BM_T + wm0 + 16 * i + g + 8 * h] = rm[i][h];
    }
    __syncthreads();
    if (tid < BM_T) {
        const float mx = fmaxf(fmaxf(red[tid], red[BM_T + tid]),
                               fmaxf(red[2 * BM_T + tid], red[3 * BM_T + tid]));
        g_mpart[(size_t)(m0 + tid) * NVT + blockIdx.x] = mx;
    }
}

// ---------------------------------------------------------------------------
// Kernel 5: g_m[r] = max over 391 tile maxima (one warp per row)
// ---------------------------------------------------------------------------
__global__ void reduce_m_kernel() {
    const int w = (blockIdx.x * blockDim.x + threadIdx.x) >> 5;
    const int lane = threadIdx.x & 31;
    if (w >= N_ROWS) return;
    float m = -CUDART_INF_F;
    for (int c = lane; c < NVT; c += 32) m = fmaxf(m, g_mpart[(size_t)w * NVT + c]);
#pragma unroll
    for (int o = 16; o; o >>= 1) m = fmaxf(m, __shfl_xor_sync(0xffffffffu, m, o));
    if (lane == 0) g_m[w] = m;
}

// ---------------------------------------------------------------------------
// Kernel 6: P~ = exp(S - m) -> bf16 hi/lo, with fused partial row sums
// ---------------------------------------------------------------------------
__global__ void expsplit_kernel() {
    const int r = blockIdx.y;
    const int tid = threadIdx.x;
    const int c = (blockIdx.x * 256 + tid) * 4;
    const float mrow = g_m[r];
    float lsum = 0.f;
    if (c < VP) {
        const float4 s = *(const float4*)(g_S + (size_t)r * VP + c);
        float p[4];
        p[0] = (c + 0 < V_SIZE) ? __expf(s.x - mrow) : 0.f;
        p[1] = (c + 1 < V_SIZE) ? __expf(s.y - mrow) : 0.f;
        p[2] = (c + 2 < V_SIZE) ? __expf(s.z - mrow) : 0.f;
        p[3] = (c + 3 < V_SIZE) ? __expf(s.w - mrow) : 0.f;
        lsum = (p[0] + p[1]) + (p[2] + p[3]);
        unsigned hi[4], lo[4];
#pragma unroll
        for (int j = 0; j < 4; ++j) {
            const __nv_bfloat16 h = __float2bfloat16(p[j]);
            hi[j] = (unsigned)__bfloat16_as_ushort(h);
            lo[j] = (unsigned)__bfloat16_as_ushort(__float2bfloat16(p[j] - __bfloat162float(h)));
        }
        uint2 hv, lv;
        hv.x = hi[0] | (hi[1] << 16); hv.y = hi[2] | (hi[3] << 16);
        lv.x = lo[0] | (lo[1] << 16); lv.y = lo[2] | (lo[3] << 16);
        *(uint2*)(g_Phi + (size_t)r * VP + c) = hv;
        *(uint2*)(g_Plo + (size_t)r * VP + c) = lv;
    }
#pragma unroll
    for (int o = 16; o; o >>= 1) lsum += __shfl_xor_sync(0xffffffffu, lsum, o);
    __shared__ float sl8[8];
    if ((tid & 31) == 0) sl8[tid >> 5] = lsum;
    __syncthreads();
    if (tid == 0) {
        float L = 0.f;
#pragma unroll
        for (int w = 0; w < 8; ++w) L += sl8[w];
        g_lpart[(size_t)r * NLT + blockIdx.x] = L;
    }
}

// ---------------------------------------------------------------------------
// Kernel 7: GEMM-2  U[split] = P~(hi/lo) @ Vocab(hi/lo); K split over vocab
// grid (DOUT/128, N_ROWS/256, NSPLIT), 512 threads
// ---------------------------------------------------------------------------
__global__ void __launch_bounds__(NTH, 1) gemm2_kernel() {
    extern __shared__ uint32_t smw[];
    const int n0 = blockIdx.x * BN_T, m0 = blockIdx.y * BM_T, sp = blockIdx.z;

    const int base = 782 / NSPLIT;
    const int rem  = 782 % NSPLIT;
    const int cbeg = sp * base + min(sp, rem);
    const int nch  = base + (sp < rem ? 1 : 0);
    const size_t k0 = (size_t)cbeg * 64;

    float acc[4][4][4];
    gemm_body(acc,
              g_Phi  + (size_t)m0 * VP + k0, g_Plo  + (size_t)m0 * VP + k0, VP,
              g_VThi + (size_t)n0 * VP + k0, g_VTlo + (size_t)n0 * VP + k0, VP,
              nch, smw);

    const int tid = threadIdx.x, wid = tid >> 5, lane = tid & 31;
    const int g = lane >> 2, t = lane & 3;
    const int wm0 = (wid >> 2) * 64, wn0 = (wid & 3) * 32;
    float* U = g_U[sp];
#pragma unroll
    for (int i = 0; i < 4; ++i) {
        const int r0 = m0 + wm0 + 16 * i + g;
#pragma unroll
        for (int j = 0; j < 4; ++j) {
            const int cc = n0 + wn0 + 8 * j + 2 * t;
            *(float2*)(U + (size_t)r0 * DOUT + cc)       = make_float2(acc[i][j][0], acc[i][j][1]);
            *(float2*)(U + (size_t)(r0 + 8) * DOUT + cc) = make_float2(acc[i][j][2], acc[i][j][3]);
        }
    }
}

// ---------------------------------------------------------------------------
// Kernel 8: final blend + normalize (l reduced from partials in-block)
// ---------------------------------------------------------------------------
__global__ void final_kernel(const float* __restrict__ words, float* __restrict__ out) {
    const int r = blockIdx.x;
    const int tid = threadIdx.x;
    __shared__ float s_l;
    if (tid < 32) {
        float L = 0.f;
        for (int c = tid; c < NLT; c += 32) L += g_lpart[(size_t)r * NLT + c];
#pragma unroll
        for (int o = 16; o; o >>= 1) L += __shfl_xor_sync(0xffffffffu, L, o);
        if (tid == 0) s_l = L;
    }
    __syncthreads();
    if (tid >= D_DIM) return;
    const float m = g_m[r];
    const float pdef = __expf(g_sdef[r] - m);
    const float inv = 1.f / (s_l + pdef);
    const int ui = r * DOUT + tid;
    float u = 0.f;
#pragma unroll
    for (int s = 0; s < NSPLIT; ++s) u += g_U[s][ui];
    out[(size_t)r * D_DIM + tid] = (u + pdef * words[(size_t)r * D_DIM + tid]) * inv;
}

// ---------------------------------------------------------------------------
// kernel_launch
// ---------------------------------------------------------------------------
extern "C" void kernel_launch(void* const* d_in, const int* in_sizes, int n_in,
                              void* d_out, int out_size) {
    const float* words = nullptr;
    const float* vocab = nullptr;
    const float* de    = nullptr;
    const float* W     = nullptr;
    for (int i = 0; i < n_in; ++i) {
        switch (in_sizes[i]) {
            case N_ROWS * D_DIM: words = (const float*)d_in[i]; break;
            case V_SIZE * D_DIM: vocab = (const float*)d_in[i]; break;
            case D_DIM:          de    = (const float*)d_in[i]; break;
            case D_DIM * D_DIM:  W     = (const float*)d_in[i]; break;
            default: break;
        }
    }
    float* out = (float*)d_out;

    y_prep_kernel<<<dim3(KP / 16, N_ROWS / 16), dim3(16, 16)>>>(words, W);
    v_prep_kernel<<<(VP * KP) / 256, 256>>>(vocab);
    vt_prep_kernel<<<(DOUT * VP) / 256, 256>>>(vocab);
    sdef_kernel<<<(N_ROWS * 32) / 256, 256>>>(de);

    cudaFuncSetAttribute(gemm1_kernel, cudaFuncAttributeMaxDynamicSharedMemorySize, GEMM_SMEM);
    gemm1_kernel<<<dim3(NVT, N_ROWS / BM_T), NTH, GEMM_SMEM>>>();

    reduce_m_kernel<<<(N_ROWS * 32) / 256, 256>>>();

    expsplit_kernel<<<dim3(NLT, N_ROWS), 256>>>();

    cudaFuncSetAttribute(gemm2_kernel, cudaFuncAttributeMaxDynamicSharedMemorySize, GEMM_SMEM);
    gemm2_kernel<<<dim3(DOUT / BN_T, N_ROWS / BM_T, NSPLIT), NTH, GEMM_SMEM>>>();

    final_kernel<<<N_ROWS, 320>>>(words, out);
}